// round 13
// baseline (speedup 1.0000x reference)
#include <cuda_runtime.h>
#include <cuda_bf16.h>

// DistortionLoss via direct-register streaming + hierarchical pairwise merge.
//   ordered split A|B:  pair(A∪B) = pair(A) + pair(B) + TW_A*TWS_B - TWS_A*TW_B
//   TW = sum w, TWS = sum w*s, s_k = z_k + z_{k+1} (raw z-space; near cancels,
//   inv = 1/(far-near) applied once).
//
// R13 = R12 without shared memory: 2 rays per warp (half-warp each), 8 elems
// per thread, ALL loads go straight from gmem to registers (2x LDG.128 for w,
// 3x overlapping aligned LDG.128 for z). No smem, no cp.async, no barriers of
// any kind -> shortest critical path (LDG -> FMA stream -> 4-level butterfly)
// and lowest instruction count (~120 issue slots per warp) of the series.

#define FULL 0xFFFFFFFFu

__global__ void __launch_bounds__(256) distortion_loss_kernel(
    const float*  __restrict__ w,     // [R,128]
    const float*  __restrict__ z,     // [R,129]
    const float*  __restrict__ nearp, // [R]
    const float*  __restrict__ farp,  // [R]
    float* __restrict__ out)          // [R]
{
    const int lane = threadIdx.x & 31;
    const int gw   = (blockIdx.x * 256 + threadIdx.x) >> 5;  // warp -> rays 2gw, 2gw+1
    const int h    = lane >> 4;                              // ray within warp
    const int t    = lane & 15;                              // thread within ray
    const int ray  = 2 * gw + h;

    // ---- w: 8 floats = 2 aligned float4s (w rows are 512B-aligned) ----
    const float4* wp = reinterpret_cast<const float4*>(w + (size_t)ray * 128 + 8 * t);
    const float4 wa = wp[0], wb = wp[1];

    // ---- z: elements 8t..8t+8 of this ray via 3 overlapping aligned quads ----
    const int f0  = ray * 129 + 8 * t;            // global float index of element 8t
    const float4* zp = reinterpret_cast<const float4*>(z) + (f0 >> 2);
    const float4 za = zp[0], zb = zp[1], zc = zp[2];
    const int off = f0 & 3;                       // = (2gw + h) & 3, half-warp uniform

    const float nr  = __ldg(nearp + ray);
    const float fr  = __ldg(farp  + ray);
    const float inv = __fdividef(1.0f, fr - nr);  // off the critical chain

    float zl[9];
    if (off == 0) {
        zl[0]=za.x; zl[1]=za.y; zl[2]=za.z; zl[3]=za.w;
        zl[4]=zb.x; zl[5]=zb.y; zl[6]=zb.z; zl[7]=zb.w; zl[8]=zc.x;
    } else if (off == 1) {
        zl[0]=za.y; zl[1]=za.z; zl[2]=za.w;
        zl[3]=zb.x; zl[4]=zb.y; zl[5]=zb.z; zl[6]=zb.w; zl[7]=zc.x; zl[8]=zc.y;
    } else if (off == 2) {
        zl[0]=za.z; zl[1]=za.w;
        zl[2]=zb.x; zl[3]=zb.y; zl[4]=zb.z; zl[5]=zb.w; zl[6]=zc.x; zl[7]=zc.y; zl[8]=zc.z;
    } else {
        zl[0]=za.w;
        zl[1]=zb.x; zl[2]=zb.y; zl[3]=zb.z; zl[4]=zb.w;
        zl[5]=zc.x; zl[6]=zc.y; zl[7]=zc.z; zl[8]=zc.w;
    }

    const float wl[8] = {wa.x, wa.y, wa.z, wa.w, wb.x, wb.y, wb.z, wb.w};

    // ---- 8-element serial stream: T (pairwise), W, WS, qq (w^2 dz) ----
    float T = 0.f, W = 0.f, WS = 0.f, qq = 0.f;
    #pragma unroll
    for (int k = 0; k < 8; k++) {
        const float wk = wl[k];
        const float s  = zl[k] + zl[k + 1];
        T  = fmaf(wk, fmaf(s, W, -WS), T);        // w_k*(s_k*W_< - WS_<)
        qq = fmaf(wk * wk, zl[k + 1] - zl[k], qq);
        W += wk;
        WS = fmaf(wk, s, WS);
    }
    T = fmaf(qq, (1.0f / 3.0f), T);               // fold linear term (merge-safe)

    // ---- 4-level xor-butterfly merge of (T, W, WS) within the 16-lane half ----
    #pragma unroll
    for (int o = 1; o < 16; o <<= 1) {
        const float pT  = __shfl_xor_sync(FULL, T,  o);
        const float pW  = __shfl_xor_sync(FULL, W,  o);
        const float pWS = __shfl_xor_sync(FULL, WS, o);
        const float c   = fmaf(W, pWS, -(WS * pW));   // TW_me*TWS_peer - TWS_me*TW_peer
        const float sgn = (t & o) ? -1.0f : 1.0f;     // lower side iff bit clear
        T = fmaf(sgn, c, T + pT);
        W  += pW;
        WS += pWS;
    }

    if (t == 0)
        out[ray] = T * inv;
}

extern "C" void kernel_launch(void* const* d_in, const int* in_sizes, int n_in,
                              void* d_out, int out_size)
{
    const float* w   = (const float*)d_in[0]; // weights [R,128,1]
    const float* z   = (const float*)d_in[1]; // z_vals  [R,129]
    const float* nr  = (const float*)d_in[2]; // near    [R,1]
    const float* fr  = (const float*)d_in[3]; // far     [R,1]
    float*       out = (float*)d_out;         // [R,1]

    const int R = in_sizes[0] / 128;          // 8192
    // 2 rays per warp, 8 warps per 256-thread CTA -> 16 rays per CTA
    distortion_loss_kernel<<<R / 16, 256>>>(w, z, nr, fr, out);
}